// round 11
// baseline (speedup 1.0000x reference)
#include <cuda_runtime.h>
#include <stdint.h>

#define RNODES 256
#define LUT_WORDS 8192            // 2^18 / 32
#define NSTEP 512
#define NSAMP 512
#define NIN 32
#define NOUT 10

// 6-bit half-groups: 43 (last covers k=252..255; k>=256 guarded to zero)
#define NH6 43
#define TAB6_ROWS (NH6 * 64)
// 12-bit groups: 21 full (g=0..20, k=0..251) + one 4-bit tail (k=252..255)
#define NG12 21
#define TAB12_TAIL (NG12 * 4096)        // 86016
#define TAB12_ROWS (TAB12_TAIL + 16)    // 86032 rows x 128 u32-pairs = 44 MB

// Static device scratch (allocation-free rule).
__device__ uint32_t g_lutbits[RNODES * LUT_WORDS];   // 8 MB bit-packed LUT (L2)
__device__ uint16_t g_tab6[TAB6_ROWS * RNODES];      // 1.4 MB half tables
__device__ uint32_t g_tab12[TAB12_ROWS * 128];       // 44 MB pair table (L2)
__device__ uint32_t g_xpack[NSAMP * NSTEP];          // per (m,s): 32 input bits
__device__ int      g_inv[RNODES];                   // node -> input slot, or -1
__device__ int      g_init[RNODES];                  // initial state bits
__device__ int      g_mode;                          // bool enc: 0=i32 1=u8 2=f32

__device__ __forceinline__ int read_bool(const void* p, long i, int mode) {
    if (mode == 0) return ((const int*)p)[i] != 0;
    if (mode == 1) return ((const unsigned char*)p)[i] != 0;
    return ((const float*)p)[i] != 0.0f;
}

__global__ void detect_kernel(const uint32_t* __restrict__ xw) {
    int lane = threadIdx.x;
    if (blockIdx.x || lane >= 32) return;
    int isf = 0, big = 0;
    for (int i = 0; i < 32; i++) {
        uint32_t v = xw[i * 32 + lane];
        if (v == 0x3f800000u) isf = 1;
        if (v > 1u) big = 1;
    }
    unsigned af = __ballot_sync(0xffffffffu, isf);
    unsigned ab = __ballot_sync(0xffffffffu, big);
    if (lane == 0) g_mode = af ? 2 : (ab ? 1 : 0);
}

// Warp-ballot LUT pack: fully coalesced 1 GB stream (DRAM-bound).
__global__ void pack_lut_kernel(const int* __restrict__ lut) {
    int gwarp = (blockIdx.x * blockDim.x + threadIdx.x) >> 5;
    int lane  = threadIdx.x & 31;
    const int* base = lut + (size_t)gwarp * 1024;
    uint32_t mine = 0;
#pragma unroll
    for (int w = 0; w < 32; w++) {
        int v = base[w * 32 + lane];
        unsigned m = __ballot_sync(0xffffffffu, v & 1);
        if (lane == w) mine = m;
    }
    g_lutbits[(size_t)gwarp * 32 + lane] = mine;
}

__global__ void pack_x_kernel(const void* __restrict__ x) {
    int gwarp = (blockIdx.x * blockDim.x + threadIdx.x) >> 5;
    int lane  = threadIdx.x & 31;
    int mode  = g_mode;
    long base = (long)gwarp * 1024;
    uint32_t mine = 0;
#pragma unroll
    for (int w = 0; w < 32; w++) {
        int v = read_bool(x, base + w * 32 + lane, mode);
        unsigned m = __ballot_sync(0xffffffffu, v);
        if (lane == w) mine = m;
    }
    g_xpack[gwarp * 32 + lane] = mine;
}

// misc (inv/init) + 6-bit half tables
#define SEC_MISC RNODES
#define SEC_T6   (TAB6_ROWS * RNODES)
__global__ void prep_small_kernel(const int* __restrict__ input_nodes,
                                  const void* __restrict__ init_res,
                                  const void* __restrict__ W,
                                  const int* __restrict__ primes) {
    int i = blockIdx.x * blockDim.x + threadIdx.x;
    int mode = g_mode;
    if (i < SEC_MISC) {
        int inv = -1;
#pragma unroll
        for (int q = 0; q < NIN; q++)
            if (input_nodes[q] == i) inv = q;
        g_inv[i] = inv;
        g_init[i] = read_bool(init_res, i, mode);
    }
    i -= SEC_MISC;
    if (i < 0 || i >= SEC_T6) return;
    // tab6 entry (h, c, node): sum over combo bits j of half-group h (k=6h+j)
    int node = i & 255;
    int c    = (i >> 8) & 63;
    int h    = i >> 14;
    uint32_t sum = 0;
#pragma unroll
    for (int j = 0; j < 6; j++) {
        int k = 6 * h + j;
        if ((c & (1 << j)) && k < RNODES) {
            if (read_bool(W, (long)node * RNODES + k, mode))
                sum += (uint32_t)primes[k];
        }
    }
    g_tab6[i] = (uint16_t)sum;
}

// Build paired 12-bit table from 6-bit halves (write-bound, 44 MB).
// Entry (row, t): u16 pair {node t, node t+128}.
__global__ void prep2_kernel() {
    int i = blockIdx.x * blockDim.x + threadIdx.x;
    if (i >= TAB12_ROWS * 128) return;
    int t   = i & 127;
    int row = i >> 7;
    uint32_t lo, hi;
    if (row < TAB12_TAIL) {
        int g  = row >> 12;
        int c  = row & 4095;
        int r0 = (2 * g) * 64 + (c & 63);
        int r1 = (2 * g + 1) * 64 + (c >> 6);
        lo = (uint32_t)g_tab6[r0 * RNODES + t]
           + (uint32_t)g_tab6[r1 * RNODES + t];
        hi = (uint32_t)g_tab6[r0 * RNODES + t + 128]
           + (uint32_t)g_tab6[r1 * RNODES + t + 128];
    } else {
        int r = 42 * 64 + (row - TAB12_TAIL);     // k = 252..255
        lo = g_tab6[r * RNODES + t];
        hi = g_tab6[r * RNODES + t + 128];
    }
    g_tab12[i] = lo | (hi << 16);
}

// 256 CTAs x 128 threads. CTA = TWO samples (A, B); thread t owns nodes
// {t, t+128} for both. Two independent chains per thread double the MLP,
// overlapping the two serial L2 round-trips across chains.
__global__ void __launch_bounds__(128, 4)
reservoir_kernel(const float* __restrict__ roW,
                 const float* __restrict__ rob,
                 float* __restrict__ out) {
    __shared__ uint32_t sh_xw[2 * NSTEP];
    __shared__ uint32_t sh_r[32];       // 2 bufs * 16 mask words (A:0-7, B:8-15)
    __shared__ float    sh_bits[2 * RNODES];

    const int t    = threadIdx.x;       // 0..127
    const int w    = t >> 5;
    const int lane = t & 31;
    const int sidA = blockIdx.x * 2;

    for (int i = t; i < 2 * NSTEP; i += 128)
        sh_xw[i] = g_xpack[sidA * NSTEP + i];   // samples A then B

    const int inv0 = g_inv[t];
    const int inv1 = g_inv[t + 128];
    unsigned bA0 = (unsigned)g_init[t];
    unsigned bA1 = (unsigned)g_init[t + 128];
    unsigned bB0 = bA0, bB1 = bA1;

    __syncthreads();

    for (int s = 0; s < NSTEP; s++) {
        // 1) input override for both chains
        uint32_t xwA = sh_xw[s];
        uint32_t xwB = sh_xw[NSTEP + s];
        unsigned aA0 = (inv0 >= 0) ? ((xwA >> inv0) & 1u) : bA0;
        unsigned aA1 = (inv1 >= 0) ? ((xwA >> inv1) & 1u) : bA1;
        unsigned aB0 = (inv0 >= 0) ? ((xwB >> inv0) & 1u) : bB0;
        unsigned aB1 = (inv1 >= 0) ? ((xwB >> inv1) & 1u) : bB1;

        // 2) state bitmask words (4 ballots), one barrier
        unsigned mA0 = __ballot_sync(0xffffffffu, aA0);
        unsigned mA1 = __ballot_sync(0xffffffffu, aA1);
        unsigned mB0 = __ballot_sync(0xffffffffu, aB0);
        unsigned mB1 = __ballot_sync(0xffffffffu, aB1);
        uint32_t* rb = sh_r + (s & 1) * 16;
        if (lane == 0) {
            rb[w]      = mA0;  rb[w + 4]  = mA1;
            rb[w + 8]  = mB0;  rb[w + 12] = mB1;
        }
        __syncthreads();

        uint4 rA0 = *(const uint4*)(rb);
        uint4 rA1 = *(const uint4*)(rb + 4);
        uint4 rB0 = *(const uint4*)(rb + 8);
        uint4 rB1 = *(const uint4*)(rb + 12);
        uint32_t wvA[8] = {rA0.x, rA0.y, rA0.z, rA0.w, rA1.x, rA1.y, rA1.z, rA1.w};
        uint32_t wvB[8] = {rB0.x, rB0.y, rB0.z, rB0.w, rB1.x, rB1.y, rB1.z, rB1.w};

        // 3) 12-bit-group pair sums, both chains interleaved (6-deep MLP/trip)
        uint32_t iA0 = 0, iA1 = 0, iB0 = 0, iB1 = 0;
#pragma unroll
        for (int trip = 0; trip < 7; trip++) {
            uint32_t accA = 0, accB = 0;  // packed u16; 3 groups max < 58.3K
#pragma unroll
            for (int j = 0; j < 3; j++) {
                int g  = trip * 3 + j;
                int bp = 12 * g;
                int wi = bp >> 5, sh = bp & 31;
                uint32_t cA = __funnelshift_r(wvA[wi], wvA[(wi + 1) & 7], sh) & 0xFFFu;
                uint32_t cB = __funnelshift_r(wvB[wi], wvB[(wi + 1) & 7], sh) & 0xFFFu;
                accA = __vadd2(accA, g_tab12[((uint32_t)g << 19) + (cA << 7) + t]);
                accB = __vadd2(accB, g_tab12[((uint32_t)g << 19) + (cB << 7) + t]);
            }
            iA0 += accA & 0xFFFFu;  iA1 += accA >> 16;
            iB0 += accB & 0xFFFFu;  iB1 += accB >> 16;
        }
        {   // tail 4-bit group (nodes k=252..255)
            uint32_t eA = g_tab12[((uint32_t)TAB12_TAIL << 7) + ((wvA[7] >> 28) << 7) + t];
            uint32_t eB = g_tab12[((uint32_t)TAB12_TAIL << 7) + ((wvB[7] >> 28) << 7) + t];
            iA0 += eA & 0xFFFFu;  iA1 += eA >> 16;
            iB0 += eB & 0xFFFFu;  iB1 += eB >> 16;
        }

        // 4) bit-packed LUT gathers: 4 independent (2 chains x 2 nodes)
        uint32_t wA0 = g_lutbits[((uint32_t)t << 13)         + (iA0 >> 5)];
        uint32_t wA1 = g_lutbits[((uint32_t)(t + 128) << 13) + (iA1 >> 5)];
        uint32_t wB0 = g_lutbits[((uint32_t)t << 13)         + (iB0 >> 5)];
        uint32_t wB1 = g_lutbits[((uint32_t)(t + 128) << 13) + (iB1 >> 5)];
        bA0 = (wA0 >> (iA0 & 31u)) & 1u;
        bA1 = (wA1 >> (iA1 & 31u)) & 1u;
        bB0 = (wB0 >> (iB0 & 31u)) & 1u;
        bB1 = (wB1 >> (iB1 & 31u)) & 1u;
    }

    // Readout for both samples
    sh_bits[t]                 = (float)bA0;
    sh_bits[t + 128]           = (float)bA1;
    sh_bits[RNODES + t]        = (float)bB0;
    sh_bits[RNODES + t + 128]  = (float)bB1;
    __syncthreads();

    if (t < 2 * NOUT) {
        int so = t / NOUT;            // 0 = A, 1 = B
        int o  = t % NOUT;
        float acc = rob[o];
        const float* wrow = roW + o * RNODES;
        const float* bb = sh_bits + so * RNODES;
#pragma unroll 8
        for (int j = 0; j < RNODES; j++)
            acc += bb[j] * wrow[j];
        out[(sidA + so) * NOUT + o] = acc;
    }
}

extern "C" void kernel_launch(void* const* d_in, const int* in_sizes, int n_in,
                              void* d_out, int out_size) {
    const void* x       = d_in[0];                   // bool [512,512,4,8] (dtype-detected)
    const int*  innod   = (const int*)d_in[1];       // int32 [32]
    const int*  lut     = (const int*)d_in[2];       // int32 [256, 262144]
    const void* W       = d_in[3];                   // bool [256,256]
    const int*  primes  = (const int*)d_in[4];       // int32 [256]
    const void* initres = d_in[5];                   // bool [256]
    const float* roW    = (const float*)d_in[6];     // f32 [10,256]
    const float* rob    = (const float*)d_in[7];     // f32 [10]
    float* out = (float*)d_out;                      // f32 [512,10]

    detect_kernel<<<1, 32>>>((const uint32_t*)x);
    pack_lut_kernel<<<8192, 256>>>(lut);             // 1 GB stream, DRAM-bound
    pack_x_kernel<<<1024, 256>>>(x);
    prep_small_kernel<<<(SEC_MISC + SEC_T6 + 255) / 256, 256>>>(innod, initres, W, primes);
    prep2_kernel<<<(TAB12_ROWS * 128 + 255) / 256, 256>>>();
    reservoir_kernel<<<NSAMP / 2, 128>>>(roW, rob, out);
}

// round 12
// speedup vs baseline: 1.0869x; 1.0869x over previous
#include <cuda_runtime.h>
#include <stdint.h>

#define RNODES 256
#define LUT_WORDS 8192            // 2^18 / 32
#define NSTEP 512
#define NSAMP 512
#define NIN 32
#define NOUT 10

// 6-bit half-groups: 43 (last covers k=252..255; k>=256 guarded to zero)
#define NH6 43
#define TAB6_ROWS (NH6 * 64)
// 12-bit groups: 21 full (g=0..20, k=0..251) + one 4-bit tail (k=252..255)
#define NG12 21
#define TAB12_TAIL (NG12 * 4096)        // 86016
#define TAB12_ROWS (TAB12_TAIL + 16)    // 86032 rows x 128 u32-pairs = 44 MB

// Static device scratch (allocation-free rule).
__device__ uint32_t g_lutbits[RNODES * LUT_WORDS];   // 8 MB bit-packed LUT (L2)
__device__ uint16_t g_tab6[TAB6_ROWS * RNODES];      // 1.4 MB half tables
__device__ uint32_t g_tab12[TAB12_ROWS * 128];       // 44 MB pair table (L2)
__device__ uint32_t g_xpack[NSAMP * NSTEP];          // per (m,s): 32 input bits
__device__ int      g_inv[RNODES];                   // node -> input slot, or -1
__device__ int      g_init[RNODES];                  // initial state bits
__device__ int      g_mode;                          // bool enc: 0=i32 1=u8 2=f32

__device__ __forceinline__ int read_bool(const void* p, long i, int mode) {
    if (mode == 0) return ((const int*)p)[i] != 0;
    if (mode == 1) return ((const unsigned char*)p)[i] != 0;
    return ((const float*)p)[i] != 0.0f;
}

__global__ void detect_kernel(const uint32_t* __restrict__ xw) {
    int lane = threadIdx.x;
    if (blockIdx.x || lane >= 32) return;
    int isf = 0, big = 0;
    for (int i = 0; i < 32; i++) {
        uint32_t v = xw[i * 32 + lane];
        if (v == 0x3f800000u) isf = 1;
        if (v > 1u) big = 1;
    }
    unsigned af = __ballot_sync(0xffffffffu, isf);
    unsigned ab = __ballot_sync(0xffffffffu, big);
    if (lane == 0) g_mode = af ? 2 : (ab ? 1 : 0);
}

// Warp-ballot LUT pack: fully coalesced 1 GB stream (DRAM-bound).
__global__ void pack_lut_kernel(const int* __restrict__ lut) {
    int gwarp = (blockIdx.x * blockDim.x + threadIdx.x) >> 5;
    int lane  = threadIdx.x & 31;
    const int* base = lut + (size_t)gwarp * 1024;
    uint32_t mine = 0;
#pragma unroll
    for (int w = 0; w < 32; w++) {
        int v = base[w * 32 + lane];
        unsigned m = __ballot_sync(0xffffffffu, v & 1);
        if (lane == w) mine = m;
    }
    g_lutbits[(size_t)gwarp * 32 + lane] = mine;
}

__global__ void pack_x_kernel(const void* __restrict__ x) {
    int gwarp = (blockIdx.x * blockDim.x + threadIdx.x) >> 5;
    int lane  = threadIdx.x & 31;
    int mode  = g_mode;
    long base = (long)gwarp * 1024;
    uint32_t mine = 0;
#pragma unroll
    for (int w = 0; w < 32; w++) {
        int v = read_bool(x, base + w * 32 + lane, mode);
        unsigned m = __ballot_sync(0xffffffffu, v);
        if (lane == w) mine = m;
    }
    g_xpack[gwarp * 32 + lane] = mine;
}

// misc (inv/init) + 6-bit half tables
#define SEC_MISC RNODES
#define SEC_T6   (TAB6_ROWS * RNODES)
__global__ void prep_small_kernel(const int* __restrict__ input_nodes,
                                  const void* __restrict__ init_res,
                                  const void* __restrict__ W,
                                  const int* __restrict__ primes) {
    int i = blockIdx.x * blockDim.x + threadIdx.x;
    int mode = g_mode;
    if (i < SEC_MISC) {
        int inv = -1;
#pragma unroll
        for (int q = 0; q < NIN; q++)
            if (input_nodes[q] == i) inv = q;
        g_inv[i] = inv;
        g_init[i] = read_bool(init_res, i, mode);
    }
    i -= SEC_MISC;
    if (i < 0 || i >= SEC_T6) return;
    // tab6 entry (h, c, node): sum over combo bits j of half-group h (k=6h+j)
    int node = i & 255;
    int c    = (i >> 8) & 63;
    int h    = i >> 14;
    uint32_t sum = 0;
#pragma unroll
    for (int j = 0; j < 6; j++) {
        int k = 6 * h + j;
        if ((c & (1 << j)) && k < RNODES) {
            if (read_bool(W, (long)node * RNODES + k, mode))
                sum += (uint32_t)primes[k];
        }
    }
    g_tab6[i] = (uint16_t)sum;
}

// Build paired 12-bit table from 6-bit halves (write-bound, 44 MB).
// Entry (row, t): u16 pair {node t, node t+128}.
__global__ void prep2_kernel() {
    int i = blockIdx.x * blockDim.x + threadIdx.x;
    if (i >= TAB12_ROWS * 128) return;
    int t   = i & 127;
    int row = i >> 7;
    uint32_t lo, hi;
    if (row < TAB12_TAIL) {
        int g  = row >> 12;
        int c  = row & 4095;
        int r0 = (2 * g) * 64 + (c & 63);
        int r1 = (2 * g + 1) * 64 + (c >> 6);
        lo = (uint32_t)g_tab6[r0 * RNODES + t]
           + (uint32_t)g_tab6[r1 * RNODES + t];
        hi = (uint32_t)g_tab6[r0 * RNODES + t + 128]
           + (uint32_t)g_tab6[r1 * RNODES + t + 128];
    } else {
        int r = 42 * 64 + (row - TAB12_TAIL);     // k = 252..255
        lo = g_tab6[r * RNODES + t];
        hi = g_tab6[r * RNODES + t + 128];
    }
    g_tab12[i] = lo | (hi << 16);
}

// 512 CTAs x 256 threads (8 warps). CTA = one sample; thread t owns node t
// (state bit, ballot word = warp id, one LUT gather). The 22 table-group
// loads are SPLIT across the two thread-halves (11 each, same u32-pair rows,
// t2 = t & 127 -> identical L2/L1 traffic as the 128-thread version), with
// partial sums exchanged via double-buffered SMEM + a second barrier.
__global__ void __launch_bounds__(256, 4)
reservoir_kernel(const float* __restrict__ roW,
                 const float* __restrict__ rob,
                 float* __restrict__ out) {
    __shared__ uint32_t sh_xw[NSTEP];
    __shared__ uint32_t sh_r[16];        // 2 bufs * 8 mask words
    __shared__ uint32_t sh_p[2 * 512];   // 2 bufs * (2 halves * 2 parts * 128)
    __shared__ float    sh_bits[RNODES];

    const int t    = threadIdx.x;        // node 0..255
    const int t2   = t & 127;
    const int half = t >> 7;             // 0: groups 0..10, 1: groups 11..21+tail
    const int w    = t >> 5;             // warp 0..7 -> mask word w
    const int lane = t & 31;
    const int sid  = blockIdx.x;

    for (int i = t; i < NSTEP; i += 256)
        sh_xw[i] = g_xpack[sid * NSTEP + i];

    const int inv = g_inv[t];
    unsigned b    = (unsigned)g_init[t];

    __syncthreads();

    for (int s = 0; s < NSTEP; s++) {
        // 1) input override (before the matvec, as in the reference)
        uint32_t xw = sh_xw[s];
        unsigned a = (inv >= 0) ? ((xw >> inv) & 1u) : b;

        // 2) state mask word w = ballot of warp w (nodes 32w..32w+31)
        unsigned m = __ballot_sync(0xffffffffu, a);
        uint32_t* rb = sh_r + (s & 1) * 8;
        if (lane == 0) rb[w] = m;
        __syncthreads();                              // barrier 1

        uint4 ra  = *(const uint4*)(rb);
        uint4 rc  = *(const uint4*)(rb + 4);
        uint32_t wv[8] = {ra.x, ra.y, ra.z, ra.w, rc.x, rc.y, rc.z, rc.w};

        // 3) half of the 12-bit-group pair sums (11 groups per thread-half)
        uint32_t i0p = 0, i1p = 0;
        if (half == 0) {
#pragma unroll
            for (int trip = 0; trip < 4; trip++) {
                uint32_t acc = 0;   // packed u16; <=3 groups, max < 58.3K
#pragma unroll
                for (int j = 0; j < 3; j++) {
                    int g = trip * 3 + j;              // 0..11
                    if (g < 11) {
                        int bp = 12 * g;
                        int wi = bp >> 5, sh = bp & 31;
                        uint32_t c = __funnelshift_r(wv[wi], wv[(wi + 1) & 7], sh) & 0xFFFu;
                        acc = __vadd2(acc, g_tab12[((uint32_t)g << 19) + (c << 7) + t2]);
                    }
                }
                i0p += acc & 0xFFFFu;
                i1p += acc >> 16;
            }
        } else {
#pragma unroll
            for (int trip = 0; trip < 4; trip++) {
                uint32_t acc = 0;
#pragma unroll
                for (int j = 0; j < 3; j++) {
                    int g = 11 + trip * 3 + j;         // 11..22
                    if (g < 21) {
                        int bp = 12 * g;
                        int wi = bp >> 5, sh = bp & 31;
                        uint32_t c = __funnelshift_r(wv[wi], wv[(wi + 1) & 7], sh) & 0xFFFu;
                        acc = __vadd2(acc, g_tab12[((uint32_t)g << 19) + (c << 7) + t2]);
                    } else if (g == 21) {              // tail 4-bit group
                        uint32_t c = wv[7] >> 28;
                        acc = __vadd2(acc, g_tab12[((uint32_t)TAB12_TAIL << 7) + (c << 7) + t2]);
                    }
                }
                i0p += acc & 0xFFFFu;
                i1p += acc >> 16;
            }
        }

        // exchange partials: pb[producer_half*256 + part*128 + t2]
        uint32_t* pb = sh_p + (s & 1) * 512;
        pb[half * 256 + t2]       = i0p;   // part 0 (nodes 0..127)
        pb[half * 256 + 128 + t2] = i1p;   // part 1 (nodes 128..255)
        __syncthreads();                              // barrier 2

        // 4) final idx for node t (part = half), then LUT gather
        uint32_t idx = pb[half * 128 + t2] + pb[256 + half * 128 + t2];
        uint32_t wd = g_lutbits[((uint32_t)t << 13) + (idx >> 5)];
        b = (wd >> (idx & 31u)) & 1u;
    }

    // Readout: out[m, o] = sum_j rf[m,j] * roW[o,j] + rob[o]
    sh_bits[t] = (float)b;
    __syncthreads();

    if (t < NOUT) {
        float acc = rob[t];
        const float* wrow = roW + t * RNODES;
#pragma unroll 8
        for (int j = 0; j < RNODES; j++)
            acc += sh_bits[j] * wrow[j];
        out[sid * NOUT + t] = acc;
    }
}

extern "C" void kernel_launch(void* const* d_in, const int* in_sizes, int n_in,
                              void* d_out, int out_size) {
    const void* x       = d_in[0];                   // bool [512,512,4,8] (dtype-detected)
    const int*  innod   = (const int*)d_in[1];       // int32 [32]
    const int*  lut     = (const int*)d_in[2];       // int32 [256, 262144]
    const void* W       = d_in[3];                   // bool [256,256]
    const int*  primes  = (const int*)d_in[4];       // int32 [256]
    const void* initres = d_in[5];                   // bool [256]
    const float* roW    = (const float*)d_in[6];     // f32 [10,256]
    const float* rob    = (const float*)d_in[7];     // f32 [10]
    float* out = (float*)d_out;                      // f32 [512,10]

    detect_kernel<<<1, 32>>>((const uint32_t*)x);
    pack_lut_kernel<<<8192, 256>>>(lut);             // 1 GB stream, DRAM-bound
    pack_x_kernel<<<1024, 256>>>(x);
    prep_small_kernel<<<(SEC_MISC + SEC_T6 + 255) / 256, 256>>>(innod, initres, W, primes);
    prep2_kernel<<<(TAB12_ROWS * 128 + 255) / 256, 256>>>();
    reservoir_kernel<<<NSAMP, 256>>>(roW, rob, out);
}

// round 13
// speedup vs baseline: 1.1938x; 1.0984x over previous
#include <cuda_runtime.h>
#include <stdint.h>

#define RNODES 256
#define LUT_LEN 262144            // 2^18 entries per node
#define NSTEP 512
#define NSAMP 512
#define NIN 32
#define NOUT 10

// LUT window: ±24576 around per-node center -> 49152 values = 1536 words
#define WIN_VALS 49152
#define WIN_WORDS 1536

// 6-bit half-groups: 43 (last covers k=252..255; k>=256 guarded to zero)
#define NH6 43
#define TAB6_ROWS (NH6 * 64)
// 12-bit groups: 21 full (g=0..20, k=0..251) + one 4-bit tail (k=252..255)
#define NG12 21
#define TAB12_TAIL (NG12 * 4096)        // 86016
#define TAB12_ROWS (TAB12_TAIL + 16)    // 86032 rows x 128 u32-pairs = 44 MB

// Static device scratch (allocation-free rule).
__device__ uint32_t g_win[RNODES * WIN_WORDS];       // 1.5 MB windowed LUT bits
__device__ uint32_t g_lo[RNODES];                    // per-node window base
__device__ uint16_t g_tab6[TAB6_ROWS * RNODES];      // 1.4 MB half tables
__device__ uint32_t g_tab12[TAB12_ROWS * 128];       // 44 MB pair table (L2)
__device__ uint32_t g_xpack[NSAMP * NSTEP];          // per (m,s): 32 input bits
__device__ int      g_inv[RNODES];                   // node -> input slot, or -1
__device__ int      g_init[RNODES];                  // initial state bits
__device__ int      g_mode;                          // bool enc: 0=i32 1=u8 2=f32

__device__ __forceinline__ int read_bool(const void* p, long i, int mode) {
    if (mode == 0) return ((const int*)p)[i] != 0;
    if (mode == 1) return ((const unsigned char*)p)[i] != 0;
    return ((const float*)p)[i] != 0.0f;
}

__global__ void detect_kernel(const uint32_t* __restrict__ xw) {
    int lane = threadIdx.x;
    if (blockIdx.x || lane >= 32) return;
    int isf = 0, big = 0;
    for (int i = 0; i < 32; i++) {
        uint32_t v = xw[i * 32 + lane];
        if (v == 0x3f800000u) isf = 1;
        if (v > 1u) big = 1;
    }
    unsigned af = __ballot_sync(0xffffffffu, isf);
    unsigned ab = __ballot_sync(0xffffffffu, big);
    if (lane == 0) g_mode = af ? 2 : (ab ? 1 : 0);
}

// Per-node window base: lo_t = clamp(c_t - 24576), c_t = (sum primes*W)/2.
// Also inv/init. One thread per node.
__global__ void center_kernel(const void* __restrict__ W,
                              const int* __restrict__ primes,
                              const int* __restrict__ input_nodes,
                              const void* __restrict__ init_res) {
    int t = blockIdx.x * blockDim.x + threadIdx.x;
    if (t >= RNODES) return;
    int mode = g_mode;
    long row = (long)t * RNODES;
    uint32_t sum = 0;
    for (int k = 0; k < RNODES; k++)
        if (read_bool(W, row + k, mode)) sum += (uint32_t)primes[k];
    int c = (int)(sum / 2);
    int lo = c - (WIN_VALS / 2);
    if (lo < 0) lo = 0;
    if (lo > LUT_LEN - WIN_VALS) lo = LUT_LEN - WIN_VALS;
    lo &= ~31;                                // word-align
    g_lo[t] = (uint32_t)lo;

    int inv = -1;
#pragma unroll
    for (int q = 0; q < NIN; q++)
        if (input_nodes[q] == t) inv = q;
    g_inv[t] = inv;
    g_init[t] = read_bool(init_res, t, mode);
}

// Pack the 48 MB of windowed LUT columns (warp-ballot, fully coalesced).
// 12288 warps: warp gw -> node gw/48, chunk gw%48 (32 words = 1024 values).
__global__ void pack_win_kernel(const int* __restrict__ lut) {
    int gw   = (blockIdx.x * blockDim.x + threadIdx.x) >> 5;
    int lane = threadIdx.x & 31;
    if (gw >= RNODES * 48) return;
    int node = gw / 48, chunk = gw % 48;
    const int* src = lut + (size_t)node * LUT_LEN + g_lo[node] + chunk * 1024;
    uint32_t mine = 0;
#pragma unroll
    for (int w = 0; w < 32; w++) {
        int v = src[w * 32 + lane];
        unsigned m = __ballot_sync(0xffffffffu, v & 1);
        if (lane == w) mine = m;
    }
    g_win[node * WIN_WORDS + chunk * 32 + lane] = mine;
}

// Warp-ballot x pack: 262144 words / 32 per warp = 8192 warps.
__global__ void pack_x_kernel(const void* __restrict__ x) {
    int gwarp = (blockIdx.x * blockDim.x + threadIdx.x) >> 5;
    int lane  = threadIdx.x & 31;
    int mode  = g_mode;
    long base = (long)gwarp * 1024;
    uint32_t mine = 0;
#pragma unroll
    for (int w = 0; w < 32; w++) {
        int v = read_bool(x, base + w * 32 + lane, mode);
        unsigned m = __ballot_sync(0xffffffffu, v);
        if (lane == w) mine = m;
    }
    g_xpack[gwarp * 32 + lane] = mine;
}

// 6-bit half tables
#define SEC_T6 (TAB6_ROWS * RNODES)
__global__ void prep_tab6_kernel(const void* __restrict__ W,
                                 const int* __restrict__ primes) {
    int i = blockIdx.x * blockDim.x + threadIdx.x;
    if (i >= SEC_T6) return;
    int mode = g_mode;
    int node = i & 255;
    int c    = (i >> 8) & 63;
    int h    = i >> 14;
    uint32_t sum = 0;
#pragma unroll
    for (int j = 0; j < 6; j++) {
        int k = 6 * h + j;
        if ((c & (1 << j)) && k < RNODES) {
            if (read_bool(W, (long)node * RNODES + k, mode))
                sum += (uint32_t)primes[k];
        }
    }
    g_tab6[i] = (uint16_t)sum;
}

// Build paired 12-bit table from 6-bit halves (write-bound, 44 MB).
__global__ void prep2_kernel() {
    int i = blockIdx.x * blockDim.x + threadIdx.x;
    if (i >= TAB12_ROWS * 128) return;
    int t   = i & 127;
    int row = i >> 7;
    uint32_t lo, hi;
    if (row < TAB12_TAIL) {
        int g  = row >> 12;
        int c  = row & 4095;
        int r0 = (2 * g) * 64 + (c & 63);
        int r1 = (2 * g + 1) * 64 + (c >> 6);
        lo = (uint32_t)g_tab6[r0 * RNODES + t]
           + (uint32_t)g_tab6[r1 * RNODES + t];
        hi = (uint32_t)g_tab6[r0 * RNODES + t + 128]
           + (uint32_t)g_tab6[r1 * RNODES + t + 128];
    } else {
        int r = 42 * 64 + (row - TAB12_TAIL);     // k = 252..255
        lo = g_tab6[r * RNODES + t];
        hi = g_tab6[r * RNODES + t + 128];
    }
    g_tab12[i] = lo | (hi << 16);
}

// 512 CTAs x 128 threads. CTA = one sample; thread t owns nodes t and t+128
// (packed u16 accumulation, spilled every 3 groups). R8 hot kernel with the
// LUT gather served from the 1.5 MB window (rare out-of-window fallback reads
// the raw int32 LUT directly).
__global__ void __launch_bounds__(128, 4)
reservoir_kernel(const int* __restrict__ lutraw,
                 const float* __restrict__ roW,
                 const float* __restrict__ rob,
                 float* __restrict__ out) {
    __shared__ uint32_t sh_xw[NSTEP];
    __shared__ uint32_t sh_r[16];       // 2 bufs * 8 mask words
    __shared__ float    sh_bits[RNODES];

    const int t    = threadIdx.x;       // 0..127
    const int w    = t >> 5;
    const int lane = t & 31;
    const int sid  = blockIdx.x;

    for (int i = t; i < NSTEP; i += 128)
        sh_xw[i] = g_xpack[sid * NSTEP + i];

    const int inv0 = g_inv[t];
    const int inv1 = g_inv[t + 128];
    const uint32_t lo0 = g_lo[t];
    const uint32_t lo1 = g_lo[t + 128];
    unsigned b0 = (unsigned)g_init[t];
    unsigned b1 = (unsigned)g_init[t + 128];

    __syncthreads();

    for (int s = 0; s < NSTEP; s++) {
        // 1) input override (before the matvec, as in the reference)
        uint32_t xw = sh_xw[s];
        unsigned a0 = (inv0 >= 0) ? ((xw >> inv0) & 1u) : b0;
        unsigned a1 = (inv1 >= 0) ? ((xw >> inv1) & 1u) : b1;

        // 2) state bitmask words: warp w -> words w and w+4
        unsigned m0 = __ballot_sync(0xffffffffu, a0);
        unsigned m1 = __ballot_sync(0xffffffffu, a1);
        uint32_t* rb = sh_r + (s & 1) * 8;
        if (lane == 0) { rb[w] = m0; rb[w + 4] = m1; }
        __syncthreads();

        uint4 ra  = *(const uint4*)(rb);
        uint4 rb4 = *(const uint4*)(rb + 4);
        uint32_t wv[8] = {ra.x, ra.y, ra.z, ra.w, rb4.x, rb4.y, rb4.z, rb4.w};

        // 3) 12-bit-group pair sums: 22 independent coalesced LDG.32
        uint32_t i0 = 0, i1 = 0;
#pragma unroll
        for (int trip = 0; trip < 7; trip++) {
            uint32_t acc = 0;   // packed u16; 3 groups max < 58.3K
#pragma unroll
            for (int j = 0; j < 3; j++) {
                int g  = trip * 3 + j;
                int bp = 12 * g;
                int wi = bp >> 5, sh = bp & 31;
                uint32_t c = __funnelshift_r(wv[wi], wv[(wi + 1) & 7], sh) & 0xFFFu;
                acc = __vadd2(acc, g_tab12[((uint32_t)g << 19) + (c << 7) + t]);
            }
            i0 += acc & 0xFFFFu;
            i1 += acc >> 16;
        }
        {   // tail 4-bit group (nodes k=252..255)
            uint32_t c = wv[7] >> 28;
            uint32_t e = g_tab12[((uint32_t)TAB12_TAIL << 7) + (c << 7) + t];
            i0 += e & 0xFFFFu;
            i1 += e >> 16;
        }

        // 4) windowed LUT gather (1.5 MB, L2-resident); rare fallback to raw LUT
        uint32_t o0 = i0 - lo0;
        uint32_t o1 = i1 - lo1;
        if (o0 < (uint32_t)WIN_VALS) {
            uint32_t wd = g_win[(uint32_t)t * WIN_WORDS + (o0 >> 5)];
            b0 = (wd >> (o0 & 31u)) & 1u;
        } else {
            b0 = (unsigned)(lutraw[(size_t)t * LUT_LEN + i0] & 1);
        }
        if (o1 < (uint32_t)WIN_VALS) {
            uint32_t wd = g_win[(uint32_t)(t + 128) * WIN_WORDS + (o1 >> 5)];
            b1 = (wd >> (o1 & 31u)) & 1u;
        } else {
            b1 = (unsigned)(lutraw[(size_t)(t + 128) * LUT_LEN + i1] & 1);
        }
    }

    // Readout: out[m, o] = sum_j rf[m,j] * roW[o,j] + rob[o]
    sh_bits[t]       = (float)b0;
    sh_bits[t + 128] = (float)b1;
    __syncthreads();

    if (t < NOUT) {
        float acc = rob[t];
        const float* wrow = roW + t * RNODES;
#pragma unroll 8
        for (int j = 0; j < RNODES; j++)
            acc += sh_bits[j] * wrow[j];
        out[sid * NOUT + t] = acc;
    }
}

extern "C" void kernel_launch(void* const* d_in, const int* in_sizes, int n_in,
                              void* d_out, int out_size) {
    const void* x       = d_in[0];                   // bool [512,512,4,8] (dtype-detected)
    const int*  innod   = (const int*)d_in[1];       // int32 [32]
    const int*  lut     = (const int*)d_in[2];       // int32 [256, 262144]
    const void* W       = d_in[3];                   // bool [256,256]
    const int*  primes  = (const int*)d_in[4];       // int32 [256]
    const void* initres = d_in[5];                   // bool [256]
    const float* roW    = (const float*)d_in[6];     // f32 [10,256]
    const float* rob    = (const float*)d_in[7];     // f32 [10]
    float* out = (float*)d_out;                      // f32 [512,10]

    detect_kernel<<<1, 32>>>((const uint32_t*)x);
    center_kernel<<<1, 256>>>(W, primes, innod, initres);
    pack_win_kernel<<<(RNODES * 48 * 32 + 255) / 256, 256>>>(lut);  // 48 MB read
    pack_x_kernel<<<1024, 256>>>(x);
    prep_tab6_kernel<<<(SEC_T6 + 255) / 256, 256>>>(W, primes);
    prep2_kernel<<<(TAB12_ROWS * 128 + 255) / 256, 256>>>();
    reservoir_kernel<<<NSAMP, 128>>>(lut, roW, rob, out);
}

// round 14
// speedup vs baseline: 1.2151x; 1.0178x over previous
#include <cuda_runtime.h>
#include <stdint.h>

#define RNODES 256
#define LUT_LEN 262144            // 2^18 entries per node
#define NSTEP 512
#define NSAMP 512
#define NIN 32
#define NOUT 10

// LUT window: ±24576 around per-node center -> 49152 values = 1536 words
#define WIN_VALS 49152
#define WIN_WORDS 1536

// 6-bit half-groups: 43 (last covers k=252..255; k>=256 guarded to zero)
#define NH6 43
#define TAB6_ROWS (NH6 * 64)
// 12-bit groups: 21 full (g=0..20, k=0..251) + one 4-bit tail (k=252..255)
#define NG12 21
#define TAB12_TAIL (NG12 * 4096)        // 86016
#define TAB12_ROWS (TAB12_TAIL + 16)    // 86032 rows x 128 u32-pairs = 44 MB

// Static device scratch (allocation-free rule).
__device__ uint32_t g_win[RNODES * WIN_WORDS];       // 1.5 MB windowed LUT bits
__device__ uint32_t g_lo[RNODES];                    // per-node window base
__device__ uint16_t g_tab6[TAB6_ROWS * RNODES];      // 1.4 MB half tables
__device__ uint32_t g_tab12[TAB12_ROWS * 128];       // 44 MB pair table (L2)
__device__ uint32_t g_xpack[NSAMP * NSTEP];          // per (m,s): 32 input bits
__device__ int      g_inv[RNODES];                   // node -> input slot, or -1
__device__ int      g_init[RNODES];                  // initial state bits
__device__ int      g_mode;                          // bool enc: 0=i32 1=u8 2=f32

__device__ __forceinline__ int read_bool(const void* p, long i, int mode) {
    if (mode == 0) return ((const int*)p)[i] != 0;
    if (mode == 1) return ((const unsigned char*)p)[i] != 0;
    return ((const float*)p)[i] != 0.0f;
}

__global__ void detect_kernel(const uint32_t* __restrict__ xw) {
    int lane = threadIdx.x;
    if (blockIdx.x || lane >= 32) return;
    int isf = 0, big = 0;
    for (int i = 0; i < 32; i++) {
        uint32_t v = xw[i * 32 + lane];
        if (v == 0x3f800000u) isf = 1;
        if (v > 1u) big = 1;
    }
    unsigned af = __ballot_sync(0xffffffffu, isf);
    unsigned ab = __ballot_sync(0xffffffffu, big);
    if (lane == 0) g_mode = af ? 2 : (ab ? 1 : 0);
}

// Per-node window base: lo_t = clamp(c_t - 24576), c_t = (sum primes*W)/2.
// Also inv/init. One thread per node.
__global__ void center_kernel(const void* __restrict__ W,
                              const int* __restrict__ primes,
                              const int* __restrict__ input_nodes,
                              const void* __restrict__ init_res) {
    int t = blockIdx.x * blockDim.x + threadIdx.x;
    if (t >= RNODES) return;
    int mode = g_mode;
    long row = (long)t * RNODES;
    uint32_t sum = 0;
    for (int k = 0; k < RNODES; k++)
        if (read_bool(W, row + k, mode)) sum += (uint32_t)primes[k];
    int c = (int)(sum / 2);
    int lo = c - (WIN_VALS / 2);
    if (lo < 0) lo = 0;
    if (lo > LUT_LEN - WIN_VALS) lo = LUT_LEN - WIN_VALS;
    lo &= ~31;                                // word-align
    g_lo[t] = (uint32_t)lo;

    int inv = -1;
#pragma unroll
    for (int q = 0; q < NIN; q++)
        if (input_nodes[q] == t) inv = q;
    g_inv[t] = inv;
    g_init[t] = read_bool(init_res, t, mode);
}

// Pack the 48 MB of windowed LUT columns (warp-ballot, fully coalesced).
// 12288 warps: warp gw -> node gw/48, chunk gw%48 (32 words = 1024 values).
__global__ void pack_win_kernel(const int* __restrict__ lut) {
    int gw   = (blockIdx.x * blockDim.x + threadIdx.x) >> 5;
    int lane = threadIdx.x & 31;
    if (gw >= RNODES * 48) return;
    int node = gw / 48, chunk = gw % 48;
    const int* src = lut + (size_t)node * LUT_LEN + g_lo[node] + chunk * 1024;
    uint32_t mine = 0;
#pragma unroll
    for (int w = 0; w < 32; w++) {
        int v = src[w * 32 + lane];
        unsigned m = __ballot_sync(0xffffffffu, v & 1);
        if (lane == w) mine = m;
    }
    g_win[node * WIN_WORDS + chunk * 32 + lane] = mine;
}

// Warp-ballot x pack: 262144 words / 32 per warp = 8192 warps.
__global__ void pack_x_kernel(const void* __restrict__ x) {
    int gwarp = (blockIdx.x * blockDim.x + threadIdx.x) >> 5;
    int lane  = threadIdx.x & 31;
    int mode  = g_mode;
    long base = (long)gwarp * 1024;
    uint32_t mine = 0;
#pragma unroll
    for (int w = 0; w < 32; w++) {
        int v = read_bool(x, base + w * 32 + lane, mode);
        unsigned m = __ballot_sync(0xffffffffu, v);
        if (lane == w) mine = m;
    }
    g_xpack[gwarp * 32 + lane] = mine;
}

// 6-bit half tables
#define SEC_T6 (TAB6_ROWS * RNODES)
__global__ void prep_tab6_kernel(const void* __restrict__ W,
                                 const int* __restrict__ primes) {
    int i = blockIdx.x * blockDim.x + threadIdx.x;
    if (i >= SEC_T6) return;
    int mode = g_mode;
    int node = i & 255;
    int c    = (i >> 8) & 63;
    int h    = i >> 14;
    uint32_t sum = 0;
#pragma unroll
    for (int j = 0; j < 6; j++) {
        int k = 6 * h + j;
        if ((c & (1 << j)) && k < RNODES) {
            if (read_bool(W, (long)node * RNODES + k, mode))
                sum += (uint32_t)primes[k];
        }
    }
    g_tab6[i] = (uint16_t)sum;
}

// Build paired 12-bit table from 6-bit halves (write-bound, 44 MB).
__global__ void prep2_kernel() {
    int i = blockIdx.x * blockDim.x + threadIdx.x;
    if (i >= TAB12_ROWS * 128) return;
    int t   = i & 127;
    int row = i >> 7;
    uint32_t lo, hi;
    if (row < TAB12_TAIL) {
        int g  = row >> 12;
        int c  = row & 4095;
        int r0 = (2 * g) * 64 + (c & 63);
        int r1 = (2 * g + 1) * 64 + (c >> 6);
        lo = (uint32_t)g_tab6[r0 * RNODES + t]
           + (uint32_t)g_tab6[r1 * RNODES + t];
        hi = (uint32_t)g_tab6[r0 * RNODES + t + 128]
           + (uint32_t)g_tab6[r1 * RNODES + t + 128];
    } else {
        int r = 42 * 64 + (row - TAB12_TAIL);     // k = 252..255
        lo = g_tab6[r * RNODES + t];
        hi = g_tab6[r * RNODES + t + 128];
    }
    g_tab12[i] = lo | (hi << 16);
}

// 512 CTAs x 128 threads. CTA = one sample; thread t owns nodes t and t+128.
// R8 hot kernel; LUT gather is branch-FREE: SEL picks window-word address vs
// raw-LUT int32 address (both single 32-bit loads), SEL picks the shift.
__global__ void __launch_bounds__(128, 4)
reservoir_kernel(const int* __restrict__ lutraw,
                 const float* __restrict__ roW,
                 const float* __restrict__ rob,
                 float* __restrict__ out) {
    __shared__ uint32_t sh_xw[NSTEP];
    __shared__ uint32_t sh_r[16];       // 2 bufs * 8 mask words
    __shared__ float    sh_bits[RNODES];

    const int t    = threadIdx.x;       // 0..127
    const int w    = t >> 5;
    const int lane = t & 31;
    const int sid  = blockIdx.x;

    for (int i = t; i < NSTEP; i += 128)
        sh_xw[i] = g_xpack[sid * NSTEP + i];

    const int inv0 = g_inv[t];
    const int inv1 = g_inv[t + 128];
    const uint32_t lo0 = g_lo[t];
    const uint32_t lo1 = g_lo[t + 128];
    const uint32_t* win0 = g_win + (uint32_t)t * WIN_WORDS;
    const uint32_t* win1 = g_win + (uint32_t)(t + 128) * WIN_WORDS;
    const uint32_t* raw0 = (const uint32_t*)(lutraw + (size_t)t * LUT_LEN);
    const uint32_t* raw1 = (const uint32_t*)(lutraw + (size_t)(t + 128) * LUT_LEN);
    unsigned b0 = (unsigned)g_init[t];
    unsigned b1 = (unsigned)g_init[t + 128];

    __syncthreads();

    for (int s = 0; s < NSTEP; s++) {
        // 1) input override (before the matvec, as in the reference)
        uint32_t xw = sh_xw[s];
        unsigned a0 = (inv0 >= 0) ? ((xw >> inv0) & 1u) : b0;
        unsigned a1 = (inv1 >= 0) ? ((xw >> inv1) & 1u) : b1;

        // 2) state bitmask words: warp w -> words w and w+4
        unsigned m0 = __ballot_sync(0xffffffffu, a0);
        unsigned m1 = __ballot_sync(0xffffffffu, a1);
        uint32_t* rb = sh_r + (s & 1) * 8;
        if (lane == 0) { rb[w] = m0; rb[w + 4] = m1; }
        __syncthreads();

        uint4 ra  = *(const uint4*)(rb);
        uint4 rb4 = *(const uint4*)(rb + 4);
        uint32_t wv[8] = {ra.x, ra.y, ra.z, ra.w, rb4.x, rb4.y, rb4.z, rb4.w};

        // 3) 12-bit-group pair sums: 22 independent coalesced LDG.32
        uint32_t i0 = 0, i1 = 0;
#pragma unroll
        for (int trip = 0; trip < 7; trip++) {
            uint32_t acc = 0;   // packed u16; 3 groups max < 58.3K
#pragma unroll
            for (int j = 0; j < 3; j++) {
                int g  = trip * 3 + j;
                int bp = 12 * g;
                int wi = bp >> 5, sh = bp & 31;
                uint32_t c = __funnelshift_r(wv[wi], wv[(wi + 1) & 7], sh) & 0xFFFu;
                acc = __vadd2(acc, g_tab12[((uint32_t)g << 19) + (c << 7) + t]);
            }
            i0 += acc & 0xFFFFu;
            i1 += acc >> 16;
        }
        {   // tail 4-bit group (nodes k=252..255)
            uint32_t c = wv[7] >> 28;
            uint32_t e = g_tab12[((uint32_t)TAB12_TAIL << 7) + (c << 7) + t];
            i0 += e & 0xFFFFu;
            i1 += e >> 16;
        }

        // 4) branch-free windowed LUT gather: SEL address + SEL shift, one LDG
        uint32_t o0 = i0 - lo0;
        uint32_t o1 = i1 - lo1;
        bool in0 = o0 < (uint32_t)WIN_VALS;
        bool in1 = o1 < (uint32_t)WIN_VALS;
        const uint32_t* p0 = in0 ? (win0 + (o0 >> 5)) : (raw0 + i0);
        const uint32_t* p1 = in1 ? (win1 + (o1 >> 5)) : (raw1 + i1);
        uint32_t sh0 = in0 ? (o0 & 31u) : 0u;
        uint32_t sh1 = in1 ? (o1 & 31u) : 0u;
        b0 = ((*p0) >> sh0) & 1u;
        b1 = ((*p1) >> sh1) & 1u;
    }

    // Readout: out[m, o] = sum_j rf[m,j] * roW[o,j] + rob[o]
    sh_bits[t]       = (float)b0;
    sh_bits[t + 128] = (float)b1;
    __syncthreads();

    if (t < NOUT) {
        float acc = rob[t];
        const float* wrow = roW + t * RNODES;
#pragma unroll 8
        for (int j = 0; j < RNODES; j++)
            acc += sh_bits[j] * wrow[j];
        out[sid * NOUT + t] = acc;
    }
}

extern "C" void kernel_launch(void* const* d_in, const int* in_sizes, int n_in,
                              void* d_out, int out_size) {
    const void* x       = d_in[0];                   // bool [512,512,4,8] (dtype-detected)
    const int*  innod   = (const int*)d_in[1];       // int32 [32]
    const int*  lut     = (const int*)d_in[2];       // int32 [256, 262144]
    const void* W       = d_in[3];                   // bool [256,256]
    const int*  primes  = (const int*)d_in[4];       // int32 [256]
    const void* initres = d_in[5];                   // bool [256]
    const float* roW    = (const float*)d_in[6];     // f32 [10,256]
    const float* rob    = (const float*)d_in[7];     // f32 [10]
    float* out = (float*)d_out;                      // f32 [512,10]

    detect_kernel<<<1, 32>>>((const uint32_t*)x);
    center_kernel<<<1, 256>>>(W, primes, innod, initres);
    pack_win_kernel<<<(RNODES * 48 * 32 + 255) / 256, 256>>>(lut);  // 48 MB read
    pack_x_kernel<<<1024, 256>>>(x);
    prep_tab6_kernel<<<(SEC_T6 + 255) / 256, 256>>>(W, primes);
    prep2_kernel<<<(TAB12_ROWS * 128 + 255) / 256, 256>>>();
    reservoir_kernel<<<NSAMP, 128>>>(lut, roW, rob, out);
}